// round 6
// baseline (speedup 1.0000x reference)
#include <cuda_runtime.h>
#include <cuda_bf16.h>
#include <math.h>
#include <stdint.h>

#define NN   100000
#define EE   1600000
#define ET   1700000      // EE + NN self loops
#define FIN  512
#define HD   64           // H1*D1
#define H1   8
#define D1   8
#define CC   16
#define NB   ((NN + 255) / 256)   // 391 scan blocks

// ---------------- scratch (static device memory; no allocations) ----------------
__device__ int   g_flag;
__device__ int   g_src[ET];
__device__ int   g_dst[ET];
__device__ int   g_col[ET];
__device__ int   g_counts[NN];
__device__ int   g_cursor[NN];
__device__ int   g_rowptr[NN + 1];
__device__ int   g_bsum[NB];
__device__ int   g_boff[NB];
__device__ float g_h1[(size_t)NN * HD];
__device__ float g_h1act[(size_t)NN * HD];
__device__ float g_es1[(size_t)NN * H1];
__device__ float g_ed1[(size_t)NN * H1];
__device__ float g_h2[(size_t)NN * CC];
__device__ float g_es2[NN];
__device__ float g_ed2[NN];

// ---------------- init: zero counts + parallel dtype detection ----------------
__global__ __launch_bounds__(256) void init_kernel(const int* ei32) {
    int i = blockIdx.x * blockDim.x + threadIdx.x;
    if (i < NN) g_counts[i] = 0;
    if (blockIdx.x == 0 && threadIdx.x < 32) {
        int lane = threadIdx.x;
        int bad = 0;
        for (int j = lane; j < 256; j += 32) {
            int k = j * 6250;
            if (ei32[2 * k + 1] != 0) bad = 1;
        }
        unsigned b = __ballot_sync(0xffffffffu, bad);
        if (lane == 0) g_flag = (b == 0) ? 1 : 0;
    }
}

// ---------------- convert + histogram in one edge pass ----------------
__global__ __launch_bounds__(256) void convert_hist_kernel(const void* ei) {
    int e = blockIdx.x * blockDim.x + threadIdx.x;
    if (e >= ET) return;
    int s, d;
    if (e < EE) {
        if (g_flag) {
            const long long* p = (const long long*)ei;
            s = (int)p[e]; d = (int)p[EE + e];
        } else {
            const int* p = (const int*)ei;
            s = p[e]; d = p[EE + e];
        }
    } else {
        s = e - EE; d = e - EE;
    }
    g_src[e] = s; g_dst[e] = d;
    atomicAdd(&g_counts[d], 1);
}

// ---------------- parallel scan: partial sums -> block scan -> apply ----------------
__global__ __launch_bounds__(256) void scan_partial_kernel() {
    __shared__ int wsum[8];
    int t = threadIdx.x;
    int i = blockIdx.x * 256 + t;
    int c = (i < NN) ? g_counts[i] : 0;
    int v = c;
    #pragma unroll
    for (int off = 1; off < 32; off <<= 1) v += __shfl_xor_sync(0xffffffffu, v, off);
    if ((t & 31) == 0) wsum[t >> 5] = v;
    __syncthreads();
    if (t == 0) {
        int s = 0;
        #pragma unroll
        for (int w = 0; w < 8; w++) s += wsum[w];
        g_bsum[blockIdx.x] = s;
    }
}

__global__ __launch_bounds__(512) void scan_blocks_kernel() {
    __shared__ int sh[512];
    int t = threadIdx.x;
    sh[t] = (t < NB) ? g_bsum[t] : 0;
    __syncthreads();
    for (int off = 1; off < 512; off <<= 1) {
        int v = (t >= off) ? sh[t - off] : 0;
        __syncthreads();
        sh[t] += v;
        __syncthreads();
    }
    if (t < NB) g_boff[t] = (t == 0) ? 0 : sh[t - 1];   // exclusive
}

__global__ __launch_bounds__(256) void scan_apply_kernel() {
    __shared__ int woff[8];
    int t = threadIdx.x, lane = t & 31, wid = t >> 5;
    int i = blockIdx.x * 256 + t;
    int c = (i < NN) ? g_counts[i] : 0;
    int incl = c;
    #pragma unroll
    for (int off = 1; off < 32; off <<= 1) {
        int v = __shfl_up_sync(0xffffffffu, incl, off);
        if (lane >= off) incl += v;
    }
    if (lane == 31) woff[wid] = incl;
    __syncthreads();
    if (t == 0) {
        int run = 0;
        #pragma unroll
        for (int w = 0; w < 8; w++) { int v = woff[w]; woff[w] = run; run += v; }
    }
    __syncthreads();
    int excl = incl - c + woff[wid] + g_boff[blockIdx.x];
    if (i < NN) { g_rowptr[i] = excl; g_cursor[i] = excl; }
    if (i == NN - 1) g_rowptr[NN] = ET;
}

__global__ __launch_bounds__(256) void scatter_kernel() {
    int e = blockIdx.x * blockDim.x + threadIdx.x;
    if (e < ET) {
        int d = g_dst[e];
        int pos = atomicAdd(&g_cursor[d], 1);
        g_col[pos] = g_src[e];
    }
}

// ---------------- GEMM1 via mma.sync split-bf16 + fused es/ed ----------------
#define KC 256
#define ST 264
#define G1_SMEM (2 * 64 * ST * 2)

__device__ __forceinline__ void cvt_pair(float vx, float vy, uint32_t& hi, uint32_t& lo) {
    asm("cvt.rn.bf16x2.f32 %0, %1, %2;" : "=r"(hi) : "f"(vy), "f"(vx));
    float h0 = __uint_as_float(hi << 16);
    float h1 = __uint_as_float(hi & 0xFFFF0000u);
    float r0 = vx - h0, r1 = vy - h1;
    asm("cvt.rn.bf16x2.f32 %0, %1, %2;" : "=r"(lo) : "f"(r1), "f"(r0));
}

__device__ __forceinline__ void mma16816(float* c, const uint32_t* a, uint32_t b0, uint32_t b1) {
    asm volatile(
        "mma.sync.aligned.m16n8k16.row.col.f32.bf16.bf16.f32 "
        "{%0,%1,%2,%3}, {%4,%5,%6,%7}, {%8,%9}, {%0,%1,%2,%3};"
        : "+f"(c[0]), "+f"(c[1]), "+f"(c[2]), "+f"(c[3])
        : "r"(a[0]), "r"(a[1]), "r"(a[2]), "r"(a[3]), "r"(b0), "r"(b1));
}

__global__ __launch_bounds__(256, 2) void gemm1_mma_kernel(const float* __restrict__ x,
                                                           const float* __restrict__ W,
                                                           const float* __restrict__ a1s,
                                                           const float* __restrict__ a1d) {
    extern __shared__ __nv_bfloat16 ws[];
    __nv_bfloat16* whi = ws;
    __nv_bfloat16* wlo = ws + 64 * ST;
    int tid = threadIdx.x;
    int wid = tid >> 5, lane = tid & 31;
    int g = lane >> 2, tc = lane & 3;
    int wm = wid & 3, wn = wid >> 2;
    int row_base = blockIdx.x * 128 + wm * 32;

    float acc[2][4][4];
    #pragma unroll
    for (int mt = 0; mt < 2; mt++)
        #pragma unroll
        for (int nt = 0; nt < 4; nt++)
            #pragma unroll
            for (int q = 0; q < 4; q++) acc[mt][nt][q] = 0.f;

    for (int ch = 0; ch < 2; ch++) {
        int kb = ch * KC;
        for (int i = tid; i < 64 * KC; i += 256) {
            int kk = i >> 6;
            int n = i & 63;
            float v = W[(size_t)(kb + kk) * HD + n];
            __nv_bfloat16 h = __float2bfloat16_rn(v);
            float r = v - __bfloat162float(h);
            whi[n * ST + kk] = h;
            wlo[n * ST + kk] = __float2bfloat16_rn(r);
        }
        __syncthreads();

        for (int ks = 0; ks < KC / 16; ks++) {
            int k0 = kb + ks * 16;
            uint32_t ah[2][4], al[2][4];
            #pragma unroll
            for (int mt = 0; mt < 2; mt++) {
                int r0 = row_base + mt * 16 + g;
                int r1 = r0 + 8;
                const float* p0 = x + (size_t)r0 * FIN + k0 + tc * 2;
                const float* p1 = x + (size_t)r1 * FIN + k0 + tc * 2;
                float2 z = make_float2(0.f, 0.f);
                float2 v0 = (r0 < NN) ? *(const float2*)p0 : z;
                float2 v1 = (r1 < NN) ? *(const float2*)p1 : z;
                float2 v2 = (r0 < NN) ? *(const float2*)(p0 + 8) : z;
                float2 v3 = (r1 < NN) ? *(const float2*)(p1 + 8) : z;
                cvt_pair(v0.x, v0.y, ah[mt][0], al[mt][0]);
                cvt_pair(v1.x, v1.y, ah[mt][1], al[mt][1]);
                cvt_pair(v2.x, v2.y, ah[mt][2], al[mt][2]);
                cvt_pair(v3.x, v3.y, ah[mt][3], al[mt][3]);
            }
            int kl = ks * 16 + tc * 2;
            #pragma unroll
            for (int nt = 0; nt < 4; nt++) {
                int n = wn * 32 + nt * 8 + g;
                const __nv_bfloat16* ph = whi + n * ST + kl;
                const __nv_bfloat16* pl = wlo + n * ST + kl;
                uint32_t bh0 = *(const uint32_t*)ph;
                uint32_t bh1 = *(const uint32_t*)(ph + 8);
                uint32_t bl0 = *(const uint32_t*)pl;
                uint32_t bl1 = *(const uint32_t*)(pl + 8);
                #pragma unroll
                for (int mt = 0; mt < 2; mt++) {
                    mma16816(acc[mt][nt], ah[mt], bh0, bh1);
                    mma16816(acc[mt][nt], al[mt], bh0, bh1);
                    mma16816(acc[mt][nt], ah[mt], bl0, bl1);
                }
            }
        }
        __syncthreads();
    }

    int col_base = wn * 32;
    #pragma unroll
    for (int mt = 0; mt < 2; mt++) {
        int r0 = row_base + mt * 16 + g;
        int r1 = r0 + 8;
        #pragma unroll
        for (int nt = 0; nt < 4; nt++) {
            int col = col_base + nt * 8 + tc * 2;
            float* c = acc[mt][nt];
            if (r0 < NN) *(float2*)(g_h1 + (size_t)r0 * HD + col) = make_float2(c[0], c[1]);
            if (r1 < NN) *(float2*)(g_h1 + (size_t)r1 * HD + col) = make_float2(c[2], c[3]);
            int head = (col_base >> 3) + nt;
            float as0 = a1s[head * 8 + tc * 2], as1 = a1s[head * 8 + tc * 2 + 1];
            float ad0 = a1d[head * 8 + tc * 2], ad1 = a1d[head * 8 + tc * 2 + 1];
            float es_a = c[0] * as0 + c[1] * as1;
            float ed_a = c[0] * ad0 + c[1] * ad1;
            float es_b = c[2] * as0 + c[3] * as1;
            float ed_b = c[2] * ad0 + c[3] * ad1;
            es_a += __shfl_xor_sync(0xffffffffu, es_a, 1); es_a += __shfl_xor_sync(0xffffffffu, es_a, 2);
            ed_a += __shfl_xor_sync(0xffffffffu, ed_a, 1); ed_a += __shfl_xor_sync(0xffffffffu, ed_a, 2);
            es_b += __shfl_xor_sync(0xffffffffu, es_b, 1); es_b += __shfl_xor_sync(0xffffffffu, es_b, 2);
            ed_b += __shfl_xor_sync(0xffffffffu, ed_b, 1); ed_b += __shfl_xor_sync(0xffffffffu, ed_b, 2);
            if (tc == 0) {
                if (r0 < NN) { g_es1[(size_t)r0 * H1 + head] = es_a; g_ed1[(size_t)r0 * H1 + head] = ed_a; }
                if (r1 < NN) { g_es1[(size_t)r1 * H1 + head] = es_b; g_ed1[(size_t)r1 * H1 + head] = ed_b; }
            }
        }
    }
}

// ---------------- layer-1 aggregation: warp/dst, 2-stream online softmax, ELU ----------------
__global__ __launch_bounds__(256) void agg1_kernel() {
    int warp = (blockIdx.x * blockDim.x + threadIdx.x) >> 5;
    int lane = threadIdx.x & 31;
    if (warp >= NN) return;
    int dst = warp;
    int head0 = lane >> 3;
    float edv = (lane < 8) ? g_ed1[(size_t)dst * H1 + lane] : 0.f;
    float mA = -INFINITY, sA = 0.f, mB = -INFINITY, sB = 0.f;
    float a0A = 0.f, a1A = 0.f, a0B = 0.f, a1B = 0.f;
    int beg = g_rowptr[dst], end = g_rowptr[dst + 1];
    int e = beg;
    for (; e + 1 < end; e += 2) {
        int srcA = g_col[e], srcB = g_col[e + 1];
        float scA = 1.f, wA = 0.f, scB = 1.f, wB = 0.f;
        if (lane < 8) {
            float evA = g_es1[(size_t)srcA * H1 + lane] + edv;
            float evB = g_es1[(size_t)srcB * H1 + lane] + edv;
            evA = evA > 0.f ? evA : 0.2f * evA;
            evB = evB > 0.f ? evB : 0.2f * evB;
            float nmA = fmaxf(mA, evA);
            float nmB = fmaxf(mB, evB);
            scA = __expf(mA - nmA); wA = __expf(evA - nmA); mA = nmA; sA = sA * scA + wA;
            scB = __expf(mB - nmB); wB = __expf(evB - nmB); mB = nmB; sB = sB * scB + wB;
        }
        float scA0 = __shfl_sync(0xffffffffu, scA, head0);
        float wA0  = __shfl_sync(0xffffffffu, wA,  head0);
        float scA1 = __shfl_sync(0xffffffffu, scA, head0 + 4);
        float wA1  = __shfl_sync(0xffffffffu, wA,  head0 + 4);
        float scB0 = __shfl_sync(0xffffffffu, scB, head0);
        float wB0  = __shfl_sync(0xffffffffu, wB,  head0);
        float scB1 = __shfl_sync(0xffffffffu, scB, head0 + 4);
        float wB1  = __shfl_sync(0xffffffffu, wB,  head0 + 4);
        float hA0 = g_h1[(size_t)srcA * HD + lane];
        float hA1 = g_h1[(size_t)srcA * HD + lane + 32];
        float hB0 = g_h1[(size_t)srcB * HD + lane];
        float hB1 = g_h1[(size_t)srcB * HD + lane + 32];
        a0A = a0A * scA0 + hA0 * wA0;
        a1A = a1A * scA1 + hA1 * wA1;
        a0B = a0B * scB0 + hB0 * wB0;
        a1B = a1B * scB1 + hB1 * wB1;
    }
    if (e < end) {
        int srcA = g_col[e];
        float scA = 1.f, wA = 0.f;
        if (lane < 8) {
            float evA = g_es1[(size_t)srcA * H1 + lane] + edv;
            evA = evA > 0.f ? evA : 0.2f * evA;
            float nmA = fmaxf(mA, evA);
            scA = __expf(mA - nmA); wA = __expf(evA - nmA); mA = nmA; sA = sA * scA + wA;
        }
        float scA0 = __shfl_sync(0xffffffffu, scA, head0);
        float wA0  = __shfl_sync(0xffffffffu, wA,  head0);
        float scA1 = __shfl_sync(0xffffffffu, scA, head0 + 4);
        float wA1  = __shfl_sync(0xffffffffu, wA,  head0 + 4);
        float hA0 = g_h1[(size_t)srcA * HD + lane];
        float hA1 = g_h1[(size_t)srcA * HD + lane + 32];
        a0A = a0A * scA0 + hA0 * wA0;
        a1A = a1A * scA1 + hA1 * wA1;
    }
    // merge streams (valid on lanes < 8)
    float fA = 1.f, fB = 0.f, s = sA;
    if (lane < 8) {
        float m = fmaxf(mA, mB);
        fA = __expf(mA - m);
        fB = __expf(mB - m);
        s = sA * fA + sB * fB;
    }
    float fA0 = __shfl_sync(0xffffffffu, fA, head0);
    float fB0 = __shfl_sync(0xffffffffu, fB, head0);
    float s0  = __shfl_sync(0xffffffffu, s,  head0);
    float fA1 = __shfl_sync(0xffffffffu, fA, head0 + 4);
    float fB1 = __shfl_sync(0xffffffffu, fB, head0 + 4);
    float s1  = __shfl_sync(0xffffffffu, s,  head0 + 4);
    float o0 = (a0A * fA0 + a0B * fB0) / s0;
    float o1 = (a1A * fA1 + a1B * fB1) / s1;
    o0 = o0 > 0.f ? o0 : expm1f(o0);
    o1 = o1 > 0.f ? o1 : expm1f(o1);
    g_h1act[(size_t)dst * HD + lane] = o0;
    g_h1act[(size_t)dst * HD + lane + 32] = o1;
}

// ---------------- GEMM2 + fused es2/ed2 ----------------
__global__ __launch_bounds__(256) void gemm2_kernel(const float* __restrict__ W2,
                                                    const float* __restrict__ a2s,
                                                    const float* __restrict__ a2d) {
    __shared__ float Ws[HD * CC];
    int t = threadIdx.x;
    {
        float4 v = ((const float4*)W2)[t];
        ((float4*)Ws)[t] = v;
    }
    __syncthreads();
    int idx = blockIdx.x * 256 + t;
    if (idx >= NN * CC) return;
    int n = idx >> 4, c = idx & 15;
    const float4* h4 = (const float4*)(g_h1act + (size_t)n * HD);
    float sum = 0.f;
    #pragma unroll
    for (int j = 0; j < 16; j++) {
        float4 v = h4[j];
        sum += v.x * Ws[(4 * j + 0) * CC + c];
        sum += v.y * Ws[(4 * j + 1) * CC + c];
        sum += v.z * Ws[(4 * j + 2) * CC + c];
        sum += v.w * Ws[(4 * j + 3) * CC + c];
    }
    g_h2[idx] = sum;
    float es = sum * a2s[c];
    float ed = sum * a2d[c];
    #pragma unroll
    for (int off = 1; off < 16; off <<= 1) {
        es += __shfl_xor_sync(0xffffffffu, es, off, 16);
        ed += __shfl_xor_sync(0xffffffffu, ed, off, 16);
    }
    if (c == 0) { g_es2[n] = es; g_ed2[n] = ed; }
}

// ---------------- layer-2 aggregation + log_softmax : half-warp/dst, 2-stream ----------------
__global__ __launch_bounds__(256) void agg2_kernel(float* __restrict__ out) {
    int gw = (blockIdx.x * blockDim.x + threadIdx.x) >> 5;
    int lane = threadIdx.x & 31;
    int half = lane >> 4;
    int r = lane & 15;
    int dst = gw * 2 + half;
    float edv = g_ed2[dst];
    float mA = -INFINITY, sA = 0.f, accA = 0.f;
    float mB = -INFINITY, sB = 0.f, accB = 0.f;
    int beg = g_rowptr[dst], end = g_rowptr[dst + 1];
    int e = beg;
    for (; e + 1 < end; e += 2) {
        int srcA = g_col[e], srcB = g_col[e + 1];
        float evA = g_es2[srcA] + edv;
        float evB = g_es2[srcB] + edv;
        evA = evA > 0.f ? evA : 0.2f * evA;
        evB = evB > 0.f ? evB : 0.2f * evB;
        float nmA = fmaxf(mA, evA);
        float nmB = fmaxf(mB, evB);
        float scA = __expf(mA - nmA), wA = __expf(evA - nmA);
        float scB = __expf(mB - nmB), wB = __expf(evB - nmB);
        mA = nmA; sA = sA * scA + wA;
        mB = nmB; sB = sB * scB + wB;
        accA = accA * scA + g_h2[(size_t)srcA * CC + r] * wA;
        accB = accB * scB + g_h2[(size_t)srcB * CC + r] * wB;
    }
    if (e < end) {
        int srcA = g_col[e];
        float evA = g_es2[srcA] + edv;
        evA = evA > 0.f ? evA : 0.2f * evA;
        float nmA = fmaxf(mA, evA);
        float scA = __expf(mA - nmA), wA = __expf(evA - nmA);
        mA = nmA; sA = sA * scA + wA;
        accA = accA * scA + g_h2[(size_t)srcA * CC + r] * wA;
    }
    float m = fmaxf(mA, mB);
    float fA = __expf(mA - m), fB = __expf(mB - m);
    float s = sA * fA + sB * fB;
    float o = (accA * fA + accB * fB) / s;
    float mx = o;
    #pragma unroll
    for (int off = 8; off; off >>= 1)
        mx = fmaxf(mx, __shfl_xor_sync(0xffffffffu, mx, off, 16));
    float se = __expf(o - mx);
    #pragma unroll
    for (int off = 8; off; off >>= 1)
        se += __shfl_xor_sync(0xffffffffu, se, off, 16);
    out[(size_t)dst * CC + r] = o - mx - logf(se);
}

// ---------------- launch ----------------
extern "C" void kernel_launch(void* const* d_in, const int* in_sizes, int n_in,
                              void* d_out, int out_size) {
    const float* x    = (const float*)d_in[0];
    const void*  ei   = d_in[1];
    const float* W1   = (const float*)d_in[2];
    const float* a1s  = (const float*)d_in[3];
    const float* a1d  = (const float*)d_in[4];
    const float* W2   = (const float*)d_in[5];
    const float* a2s  = (const float*)d_in[6];
    const float* a2d  = (const float*)d_in[7];
    float* out = (float*)d_out;

    cudaFuncSetAttribute(gemm1_mma_kernel, cudaFuncAttributeMaxDynamicSharedMemorySize, G1_SMEM);

    init_kernel<<<NB, 256>>>((const int*)ei);
    convert_hist_kernel<<<(ET + 255) / 256, 256>>>(ei);
    scan_partial_kernel<<<NB, 256>>>();
    scan_blocks_kernel<<<1, 512>>>();
    scan_apply_kernel<<<NB, 256>>>();
    scatter_kernel<<<(ET + 255) / 256, 256>>>();

    gemm1_mma_kernel<<<(NN + 127) / 128, 256, G1_SMEM>>>(x, W1, a1s, a1d);
    agg1_kernel<<<(NN * 32 + 255) / 256, 256>>>();

    gemm2_kernel<<<(NN * CC + 255) / 256, 256>>>(W2, a2s, a2d);
    agg2_kernel<<<(NN * 16 + 255) / 256, 256>>>(out);
}